// round 1
// baseline (speedup 1.0000x reference)
#include <cuda_runtime.h>
#include <cuda_bf16.h>
#include <cstdint>

// Problem constants (fixed by the dataset)
#define F_IN   512
#define F_OUT  128
#define MAX_N  50000

// Scratch for x = (features * drop_mask) @ W   [N, F_OUT]
__device__ float g_x[(size_t)MAX_N * F_OUT];

// ---------------------------------------------------------------------------
// Kernel 1: fused dropout + SGEMM (fp32)
// BM=128, BN=128(=F_OUT), BK=16, 256 threads, 8x8 micro-tile per thread.
// ---------------------------------------------------------------------------
#define BM 128
#define BN 128
#define BK 16
#define TM 8
#define TN 8

__global__ __launch_bounds__(256, 2)
void gemm_dropout_kernel(const float* __restrict__ A,
                         const float* __restrict__ Mk,
                         const float* __restrict__ W,
                         int M)
{
    __shared__ float As[BK][BM];   // transposed A tile: As[k][m]
    __shared__ float Bs[BK][BN];

    const int block_m = blockIdx.x * BM;
    const int tid = threadIdx.x;
    const int ty  = tid >> 4;      // 0..15
    const int tx  = tid & 15;      // 0..15

    float acc[TM][TN];
#pragma unroll
    for (int i = 0; i < TM; i++)
#pragma unroll
        for (int j = 0; j < TN; j++) acc[i][j] = 0.f;

    for (int k0 = 0; k0 < F_IN; k0 += BK) {
        // --- load A tile (128 x 16) with dropout fused; 512 float4, 2/thread
#pragma unroll
        for (int p = 0; p < 2; p++) {
            int idx  = tid + p * 256;        // 0..511
            int row  = idx >> 2;             // 0..127
            int col4 = (idx & 3) * 4;        // 0,4,8,12
            int gm   = block_m + row;
            float4 av = make_float4(0.f, 0.f, 0.f, 0.f);
            if (gm < M) {
                const float4 a = *(const float4*)(A  + (size_t)gm * F_IN + k0 + col4);
                const float4 m = *(const float4*)(Mk + (size_t)gm * F_IN + k0 + col4);
                av = make_float4(a.x * m.x, a.y * m.y, a.z * m.z, a.w * m.w);
            }
            As[col4 + 0][row] = av.x;
            As[col4 + 1][row] = av.y;
            As[col4 + 2][row] = av.z;
            As[col4 + 3][row] = av.w;
        }
        // --- load B tile (16 x 128); 512 float4, 2/thread
#pragma unroll
        for (int p = 0; p < 2; p++) {
            int idx  = tid + p * 256;
            int row  = idx >> 5;             // 0..15
            int col4 = (idx & 31) * 4;       // 0..124
            *(float4*)(&Bs[row][col4]) =
                *(const float4*)(W + (size_t)(k0 + row) * F_OUT + col4);
        }
        __syncthreads();

#pragma unroll
        for (int k = 0; k < BK; k++) {
            float ar[TM], br[TN];
#pragma unroll
            for (int i = 0; i < TM; i++) ar[i] = As[k][ty * TM + i];
#pragma unroll
            for (int j = 0; j < TN; j++) br[j] = Bs[k][tx * TN + j];
#pragma unroll
            for (int i = 0; i < TM; i++)
#pragma unroll
                for (int j = 0; j < TN; j++)
                    acc[i][j] = fmaf(ar[i], br[j], acc[i][j]);
        }
        __syncthreads();
    }

    // --- store x tile
#pragma unroll
    for (int i = 0; i < TM; i++) {
        int gm = block_m + ty * TM + i;
        if (gm < M) {
            float* xr = g_x + (size_t)gm * F_OUT + tx * TN;
#pragma unroll
            for (int j = 0; j < TN; j += 4)
                *(float4*)(xr + j) = make_float4(acc[i][j], acc[i][j+1],
                                                 acc[i][j+2], acc[i][j+3]);
        }
    }
}

// ---------------------------------------------------------------------------
// Kernel 2: out[n][j] = b[j]   (bias pre-seeded so scatter accumulates on top)
// ---------------------------------------------------------------------------
__global__ void init_out_kernel(float* __restrict__ out,
                                const float* __restrict__ b, int total)
{
    int i = blockIdx.x * blockDim.x + threadIdx.x;
    if (i < total) out[i] = b[i & (F_OUT - 1)];
}

// ---------------------------------------------------------------------------
// Kernel 3: edge-parallel scatter. One warp per edge; each lane handles one
// float4 (32 lanes x 4 = 128 = F_OUT). Vector reduction to global.
// ---------------------------------------------------------------------------
__global__ __launch_bounds__(256)
void scatter_kernel(const int*   __restrict__ rows,
                    const int*   __restrict__ cols,
                    const float* __restrict__ vals,
                    float*       __restrict__ out,
                    int E)
{
    int warp_g = (blockIdx.x * blockDim.x + threadIdx.x) >> 5;
    int lane   = threadIdx.x & 31;
    if (warp_g >= E) return;

    const int   r = rows[warp_g];
    const int   c = cols[warp_g];
    const float v = vals[warp_g];

    float4 a = ((const float4*)(g_x + (size_t)c * F_OUT))[lane];
    a.x *= v; a.y *= v; a.z *= v; a.w *= v;

    float4* op = (float4*)(out + (size_t)r * F_OUT) + lane;
    asm volatile("red.global.add.v4.f32 [%0], {%1, %2, %3, %4};"
                 :: "l"(op), "f"(a.x), "f"(a.y), "f"(a.z), "f"(a.w)
                 : "memory");
}

// ---------------------------------------------------------------------------
// Kernel 4: in-place ReLU
// ---------------------------------------------------------------------------
__global__ void relu_kernel(float* __restrict__ out, int total4)
{
    int i = blockIdx.x * blockDim.x + threadIdx.x;
    if (i < total4) {
        float4 v = ((float4*)out)[i];
        v.x = fmaxf(v.x, 0.f); v.y = fmaxf(v.y, 0.f);
        v.z = fmaxf(v.z, 0.f); v.w = fmaxf(v.w, 0.f);
        ((float4*)out)[i] = v;
    }
}

// ---------------------------------------------------------------------------
extern "C" void kernel_launch(void* const* d_in, const int* in_sizes, int n_in,
                              void* d_out, int out_size)
{
    const float* features = (const float*)d_in[0];   // [N, 512]
    const float* drop_mask = (const float*)d_in[1];  // [N, 512]
    const float* W         = (const float*)d_in[2];  // [512, 128]
    const float* b         = (const float*)d_in[3];  // [128]
    const int*   adj_rows  = (const int*)d_in[4];    // [E]
    const int*   adj_cols  = (const int*)d_in[5];    // [E]
    const float* adj_vals  = (const float*)d_in[6];  // [E]
    float* out = (float*)d_out;                      // [N, 128]

    const int M = in_sizes[0] / F_IN;
    const int E = in_sizes[4];

    // 1) x = (features * drop_mask) @ W
    gemm_dropout_kernel<<<(M + BM - 1) / BM, 256>>>(features, drop_mask, W, M);

    // 2) out = broadcast(b)
    const int total = M * F_OUT;
    init_out_kernel<<<(total + 255) / 256, 256>>>(out, b, total);

    // 3) out[r] += v * x[c]  for every edge (vector global reduction)
    long long threads = (long long)E * 32;
    int blocks = (int)((threads + 255) / 256);
    scatter_kernel<<<blocks, 256>>>(adj_rows, adj_cols, adj_vals, out, E);

    // 4) out = relu(out)
    relu_kernel<<<(total / 4 + 255) / 256, 256>>>(out, total / 4);
}

// round 2
// speedup vs baseline: 1.0164x; 1.0164x over previous
#include <cuda_runtime.h>
#include <cuda_bf16.h>
#include <cstdint>

// Problem constants (fixed by the dataset)
#define F_IN   512
#define F_OUT  128
#define MAX_N  50000

// Scratch for x = (features * drop_mask) @ W   [N, F_OUT]
__device__ float g_x[(size_t)MAX_N * F_OUT];

// ---------------------------------------------------------------------------
// Packed f32x2 helpers (Blackwell FFMA2 — 2x fp32 FMA throughput, exact fp32)
// ---------------------------------------------------------------------------
__device__ __forceinline__ void fma2(unsigned long long& d,
                                     unsigned long long a,
                                     unsigned long long b)
{
    asm("fma.rn.f32x2 %0, %1, %2, %0;" : "+l"(d) : "l"(a), "l"(b));
}

__device__ __forceinline__ unsigned long long splat2(float x)
{
    unsigned long long r;
    asm("mov.b64 %0, {%1, %1};" : "=l"(r) : "f"(x));
    return r;
}

__device__ __forceinline__ float2 unpack2(unsigned long long v)
{
    float2 f;
    asm("mov.b64 {%0, %1}, %2;" : "=f"(f.x), "=f"(f.y) : "l"(v));
    return f;
}

// ---------------------------------------------------------------------------
// Kernel 1: fused dropout + SGEMM (fp32, FFMA2 inner loop)
// BM=128, BN=128(=F_OUT), BK=16, 256 threads, 8x8 micro-tile per thread.
// ---------------------------------------------------------------------------
#define BM 128
#define BN 128
#define BK 16
#define TM 8
#define TN 8

__global__ __launch_bounds__(256, 2)
void gemm_dropout_kernel(const float* __restrict__ A,
                         const float* __restrict__ Mk,
                         const float* __restrict__ W,
                         int M)
{
    __shared__ float As[BK][BM];   // transposed A tile: As[k][m]
    __shared__ float Bs[BK][BN];

    const int block_m = blockIdx.x * BM;
    const int tid = threadIdx.x;
    const int ty  = tid >> 4;      // 0..15
    const int tx  = tid & 15;      // 0..15

    // Packed accumulators: pairs along N. acc2[i][j2] = (acc[i][2*j2], acc[i][2*j2+1])
    unsigned long long acc2[TM][TN / 2];
#pragma unroll
    for (int i = 0; i < TM; i++)
#pragma unroll
        for (int j = 0; j < TN / 2; j++) acc2[i][j] = 0ull;

    for (int k0 = 0; k0 < F_IN; k0 += BK) {
        // --- load A tile (128 x 16) with dropout fused; 512 float4, 2/thread
#pragma unroll
        for (int p = 0; p < 2; p++) {
            int idx  = tid + p * 256;        // 0..511
            int row  = idx >> 2;             // 0..127
            int col4 = (idx & 3) * 4;        // 0,4,8,12
            int gm   = block_m + row;
            float4 av = make_float4(0.f, 0.f, 0.f, 0.f);
            if (gm < M) {
                const float4 a = *(const float4*)(A  + (size_t)gm * F_IN + k0 + col4);
                const float4 m = *(const float4*)(Mk + (size_t)gm * F_IN + k0 + col4);
                av = make_float4(a.x * m.x, a.y * m.y, a.z * m.z, a.w * m.w);
            }
            As[col4 + 0][row] = av.x;
            As[col4 + 1][row] = av.y;
            As[col4 + 2][row] = av.z;
            As[col4 + 3][row] = av.w;
        }
        // --- load B tile (16 x 128); 512 float4, 2/thread
#pragma unroll
        for (int p = 0; p < 2; p++) {
            int idx  = tid + p * 256;
            int row  = idx >> 5;             // 0..15
            int col4 = (idx & 31) * 4;       // 0..124
            *(float4*)(&Bs[row][col4]) =
                *(const float4*)(W + (size_t)(k0 + row) * F_OUT + col4);
        }
        __syncthreads();

#pragma unroll
        for (int k = 0; k < BK; k++) {
            // A fragment: 8 contiguous floats, splatted into f32x2 pairs
            const float4 av0 = *(const float4*)(&As[k][ty * TM]);
            const float4 av1 = *(const float4*)(&As[k][ty * TM + 4]);
            unsigned long long a2[TM];
            a2[0] = splat2(av0.x); a2[1] = splat2(av0.y);
            a2[2] = splat2(av0.z); a2[3] = splat2(av0.w);
            a2[4] = splat2(av1.x); a2[5] = splat2(av1.y);
            a2[6] = splat2(av1.z); a2[7] = splat2(av1.w);

            // B fragment: 8 contiguous floats as 4 packed pairs
            const unsigned long long* bs =
                (const unsigned long long*)(&Bs[k][tx * TN]);
            unsigned long long b2[TN / 2];
            b2[0] = bs[0]; b2[1] = bs[1]; b2[2] = bs[2]; b2[3] = bs[3];

#pragma unroll
            for (int i = 0; i < TM; i++)
#pragma unroll
                for (int j = 0; j < TN / 2; j++)
                    fma2(acc2[i][j], a2[i], b2[j]);
        }
        __syncthreads();
    }

    // --- store x tile
#pragma unroll
    for (int i = 0; i < TM; i++) {
        int gm = block_m + ty * TM + i;
        if (gm < M) {
            float* xr = g_x + (size_t)gm * F_OUT + tx * TN;
#pragma unroll
            for (int j = 0; j < TN / 2; j += 2) {
                float2 lo = unpack2(acc2[i][j]);
                float2 hi = unpack2(acc2[i][j + 1]);
                *(float4*)(xr + 2 * j) = make_float4(lo.x, lo.y, hi.x, hi.y);
            }
        }
    }
}

// ---------------------------------------------------------------------------
// Kernel 2: out[n][j] = b[j]   (bias pre-seeded so scatter accumulates on top)
// ---------------------------------------------------------------------------
__global__ void init_out_kernel(float* __restrict__ out,
                                const float* __restrict__ b, int total)
{
    int i = blockIdx.x * blockDim.x + threadIdx.x;
    if (i < total) out[i] = b[i & (F_OUT - 1)];
}

// ---------------------------------------------------------------------------
// Kernel 3: edge-parallel scatter. One warp per edge; each lane handles one
// float4 (32 lanes x 4 = 128 = F_OUT). Vector reduction to global.
// ---------------------------------------------------------------------------
__global__ __launch_bounds__(256)
void scatter_kernel(const int*   __restrict__ rows,
                    const int*   __restrict__ cols,
                    const float* __restrict__ vals,
                    float*       __restrict__ out,
                    int E)
{
    int warp_g = (blockIdx.x * blockDim.x + threadIdx.x) >> 5;
    int lane   = threadIdx.x & 31;
    if (warp_g >= E) return;

    const int   r = rows[warp_g];
    const int   c = cols[warp_g];
    const float v = vals[warp_g];

    float4 a = ((const float4*)(g_x + (size_t)c * F_OUT))[lane];
    a.x *= v; a.y *= v; a.z *= v; a.w *= v;

    float4* op = (float4*)(out + (size_t)r * F_OUT) + lane;
    asm volatile("red.global.add.v4.f32 [%0], {%1, %2, %3, %4};"
                 :: "l"(op), "f"(a.x), "f"(a.y), "f"(a.z), "f"(a.w)
                 : "memory");
}

// ---------------------------------------------------------------------------
// Kernel 4: in-place ReLU
// ---------------------------------------------------------------------------
__global__ void relu_kernel(float* __restrict__ out, int total4)
{
    int i = blockIdx.x * blockDim.x + threadIdx.x;
    if (i < total4) {
        float4 v = ((float4*)out)[i];
        v.x = fmaxf(v.x, 0.f); v.y = fmaxf(v.y, 0.f);
        v.z = fmaxf(v.z, 0.f); v.w = fmaxf(v.w, 0.f);
        ((float4*)out)[i] = v;
    }
}

// ---------------------------------------------------------------------------
extern "C" void kernel_launch(void* const* d_in, const int* in_sizes, int n_in,
                              void* d_out, int out_size)
{
    const float* features  = (const float*)d_in[0];  // [N, 512]
    const float* drop_mask = (const float*)d_in[1];  // [N, 512]
    const float* W         = (const float*)d_in[2];  // [512, 128]
    const float* b         = (const float*)d_in[3];  // [128]
    const int*   adj_rows  = (const int*)d_in[4];    // [E]
    const int*   adj_cols  = (const int*)d_in[5];    // [E]
    const float* adj_vals  = (const float*)d_in[6];  // [E]
    float* out = (float*)d_out;                      // [N, 128]

    const int M = in_sizes[0] / F_IN;
    const int E = in_sizes[4];

    // 1) x = (features * drop_mask) @ W
    gemm_dropout_kernel<<<(M + BM - 1) / BM, 256>>>(features, drop_mask, W, M);

    // 2) out = broadcast(b)
    const int total = M * F_OUT;
    init_out_kernel<<<(total + 255) / 256, 256>>>(out, b, total);

    // 3) out[r] += v * x[c]  for every edge (vector global reduction)
    long long threads = (long long)E * 32;
    int blocks = (int)((threads + 255) / 256);
    scatter_kernel<<<blocks, 256>>>(adj_rows, adj_cols, adj_vals, out, E);

    // 4) out = relu(out)
    relu_kernel<<<(total / 4 + 255) / 256, 256>>>(out, total / 4);
}

// round 3
// speedup vs baseline: 1.0966x; 1.0790x over previous
#include <cuda_runtime.h>
#include <cuda_bf16.h>
#include <cstdint>

// Problem constants (fixed by the dataset)
#define F_IN   512
#define F_OUT  128
#define MAX_N  50048
#define MAX_E  1700000

// Scratch for x = (features * drop_mask) @ W   [N, F_OUT]
__device__ float g_x[(size_t)MAX_N * F_OUT];

// CSR scratch
__device__ int   g_deg[MAX_N];
__device__ int   g_row_start[MAX_N + 1];
__device__ int   g_cursor[MAX_N];
__device__ uint2 g_edges[MAX_E];   // .x = col, .y = bits(val)

// ---------------------------------------------------------------------------
// Packed f32x2 helpers (Blackwell FFMA2)
// ---------------------------------------------------------------------------
__device__ __forceinline__ void fma2(unsigned long long& d,
                                     unsigned long long a,
                                     unsigned long long b)
{
    asm("fma.rn.f32x2 %0, %1, %2, %0;" : "+l"(d) : "l"(a), "l"(b));
}

__device__ __forceinline__ unsigned long long splat2(float x)
{
    unsigned long long r;
    asm("mov.b64 %0, {%1, %1};" : "=l"(r) : "f"(x));
    return r;
}

__device__ __forceinline__ float2 unpack2(unsigned long long v)
{
    float2 f;
    asm("mov.b64 {%0, %1}, %2;" : "=f"(f.x), "=f"(f.y) : "l"(v));
    return f;
}

// ---------------------------------------------------------------------------
// Kernel 1: fused dropout + SGEMM (fp32, FFMA2 inner loop)
// ---------------------------------------------------------------------------
#define BM 128
#define BN 128
#define BK 16
#define TM 8
#define TN 8

__global__ __launch_bounds__(256, 2)
void gemm_dropout_kernel(const float* __restrict__ A,
                         const float* __restrict__ Mk,
                         const float* __restrict__ W,
                         int M)
{
    __shared__ float As[BK][BM];
    __shared__ float Bs[BK][BN];

    const int block_m = blockIdx.x * BM;
    const int tid = threadIdx.x;
    const int ty  = tid >> 4;
    const int tx  = tid & 15;

    unsigned long long acc2[TM][TN / 2];
#pragma unroll
    for (int i = 0; i < TM; i++)
#pragma unroll
        for (int j = 0; j < TN / 2; j++) acc2[i][j] = 0ull;

    for (int k0 = 0; k0 < F_IN; k0 += BK) {
#pragma unroll
        for (int p = 0; p < 2; p++) {
            int idx  = tid + p * 256;
            int row  = idx >> 2;
            int col4 = (idx & 3) * 4;
            int gm   = block_m + row;
            float4 av = make_float4(0.f, 0.f, 0.f, 0.f);
            if (gm < M) {
                const float4 a = *(const float4*)(A  + (size_t)gm * F_IN + k0 + col4);
                const float4 m = *(const float4*)(Mk + (size_t)gm * F_IN + k0 + col4);
                av = make_float4(a.x * m.x, a.y * m.y, a.z * m.z, a.w * m.w);
            }
            As[col4 + 0][row] = av.x;
            As[col4 + 1][row] = av.y;
            As[col4 + 2][row] = av.z;
            As[col4 + 3][row] = av.w;
        }
#pragma unroll
        for (int p = 0; p < 2; p++) {
            int idx  = tid + p * 256;
            int row  = idx >> 5;
            int col4 = (idx & 31) * 4;
            *(float4*)(&Bs[row][col4]) =
                *(const float4*)(W + (size_t)(k0 + row) * F_OUT + col4);
        }
        __syncthreads();

#pragma unroll
        for (int k = 0; k < BK; k++) {
            const float4 av0 = *(const float4*)(&As[k][ty * TM]);
            const float4 av1 = *(const float4*)(&As[k][ty * TM + 4]);
            unsigned long long a2[TM];
            a2[0] = splat2(av0.x); a2[1] = splat2(av0.y);
            a2[2] = splat2(av0.z); a2[3] = splat2(av0.w);
            a2[4] = splat2(av1.x); a2[5] = splat2(av1.y);
            a2[6] = splat2(av1.z); a2[7] = splat2(av1.w);

            const unsigned long long* bs =
                (const unsigned long long*)(&Bs[k][tx * TN]);
            unsigned long long b2[TN / 2];
            b2[0] = bs[0]; b2[1] = bs[1]; b2[2] = bs[2]; b2[3] = bs[3];

#pragma unroll
            for (int i = 0; i < TM; i++)
#pragma unroll
                for (int j = 0; j < TN / 2; j++)
                    fma2(acc2[i][j], a2[i], b2[j]);
        }
        __syncthreads();
    }

#pragma unroll
    for (int i = 0; i < TM; i++) {
        int gm = block_m + ty * TM + i;
        if (gm < M) {
            float* xr = g_x + (size_t)gm * F_OUT + tx * TN;
#pragma unroll
            for (int j = 0; j < TN / 2; j += 2) {
                float2 lo = unpack2(acc2[i][j]);
                float2 hi = unpack2(acc2[i][j + 1]);
                *(float4*)(xr + 2 * j) = make_float4(lo.x, lo.y, hi.x, hi.y);
            }
        }
    }
}

// ---------------------------------------------------------------------------
// CSR build step 1: zero degree counters
// ---------------------------------------------------------------------------
__global__ void zero_deg_kernel(int N)
{
    int i = blockIdx.x * blockDim.x + threadIdx.x;
    if (i < N) g_deg[i] = 0;
}

// ---------------------------------------------------------------------------
// CSR build step 2: histogram of row degrees
// ---------------------------------------------------------------------------
__global__ void hist_kernel(const int* __restrict__ rows, int E)
{
    int i = blockIdx.x * blockDim.x + threadIdx.x;
    if (i < E) atomicAdd(&g_deg[rows[i]], 1);
}

// ---------------------------------------------------------------------------
// CSR build step 3: exclusive scan (single block, 1024 threads, serial chunks)
// ---------------------------------------------------------------------------
__global__ __launch_bounds__(1024)
void scan_kernel(int N)
{
    __shared__ int partial[1024];
    const int tid = threadIdx.x;
    const int chunk = (N + 1023) / 1024;
    const int beg = tid * chunk;
    const int end = min(beg + chunk, N);

    int s = 0;
    for (int i = beg; i < end; i++) s += g_deg[i];
    partial[tid] = s;
    __syncthreads();

    // Blelloch-free simple scan: Hillis-Steele on 1024 entries
    int v = partial[tid];
#pragma unroll
    for (int off = 1; off < 1024; off <<= 1) {
        int t = (tid >= off) ? partial[tid - off] : 0;
        __syncthreads();
        v += t;
        partial[tid] = v;
        __syncthreads();
    }
    int excl = v - s;   // exclusive prefix for this chunk

    int running = excl;
    for (int i = beg; i < end; i++) {
        g_row_start[i] = running;
        g_cursor[i]    = running;
        running += g_deg[i];
    }
    if (tid == 1023) g_row_start[N] = running;
}

// ---------------------------------------------------------------------------
// CSR build step 4: bucket fill (packed col+val)
// ---------------------------------------------------------------------------
__global__ void fill_kernel(const int*   __restrict__ rows,
                            const int*   __restrict__ cols,
                            const float* __restrict__ vals,
                            int E)
{
    int i = blockIdx.x * blockDim.x + threadIdx.x;
    if (i < E) {
        int pos = atomicAdd(&g_cursor[rows[i]], 1);
        g_edges[pos] = make_uint2((unsigned)cols[i], __float_as_uint(vals[i]));
    }
}

// ---------------------------------------------------------------------------
// Kernel 5: row-parallel SpMM + bias + ReLU (one warp per output row)
// Each lane owns one float4 (32 lanes x 4 = 128 = F_OUT).
// ---------------------------------------------------------------------------
__global__ __launch_bounds__(256)
void spmm_csr_kernel(const float* __restrict__ b,
                     float*       __restrict__ out,
                     int N)
{
    const int warp_in_blk = threadIdx.x >> 5;
    const int lane = threadIdx.x & 31;
    const int row  = blockIdx.x * 8 + warp_in_blk;
    if (row >= N) return;

    const int s = g_row_start[row];
    const int e = g_row_start[row + 1];

    float4 acc = make_float4(0.f, 0.f, 0.f, 0.f);

    int j = s;
    // 2-edge unroll for memory-level parallelism
    for (; j + 2 <= e; j += 2) {
        const uint2 e0 = g_edges[j];
        const uint2 e1 = g_edges[j + 1];
        const float4 a0 = ((const float4*)(g_x + (size_t)e0.x * F_OUT))[lane];
        const float4 a1 = ((const float4*)(g_x + (size_t)e1.x * F_OUT))[lane];
        const float v0 = __uint_as_float(e0.y);
        const float v1 = __uint_as_float(e1.y);
        acc.x = fmaf(v0, a0.x, acc.x); acc.y = fmaf(v0, a0.y, acc.y);
        acc.z = fmaf(v0, a0.z, acc.z); acc.w = fmaf(v0, a0.w, acc.w);
        acc.x = fmaf(v1, a1.x, acc.x); acc.y = fmaf(v1, a1.y, acc.y);
        acc.z = fmaf(v1, a1.z, acc.z); acc.w = fmaf(v1, a1.w, acc.w);
    }
    if (j < e) {
        const uint2 e0 = g_edges[j];
        const float4 a0 = ((const float4*)(g_x + (size_t)e0.x * F_OUT))[lane];
        const float v0 = __uint_as_float(e0.y);
        acc.x = fmaf(v0, a0.x, acc.x); acc.y = fmaf(v0, a0.y, acc.y);
        acc.z = fmaf(v0, a0.z, acc.z); acc.w = fmaf(v0, a0.w, acc.w);
    }

    // fused bias + ReLU
    const float4 bb = ((const float4*)b)[lane];
    float4 r;
    r.x = fmaxf(acc.x + bb.x, 0.f);
    r.y = fmaxf(acc.y + bb.y, 0.f);
    r.z = fmaxf(acc.z + bb.z, 0.f);
    r.w = fmaxf(acc.w + bb.w, 0.f);
    ((float4*)(out + (size_t)row * F_OUT))[lane] = r;
}

// ---------------------------------------------------------------------------
extern "C" void kernel_launch(void* const* d_in, const int* in_sizes, int n_in,
                              void* d_out, int out_size)
{
    const float* features  = (const float*)d_in[0];  // [N, 512]
    const float* drop_mask = (const float*)d_in[1];  // [N, 512]
    const float* W         = (const float*)d_in[2];  // [512, 128]
    const float* b         = (const float*)d_in[3];  // [128]
    const int*   adj_rows  = (const int*)d_in[4];    // [E]
    const int*   adj_cols  = (const int*)d_in[5];    // [E]
    const float* adj_vals  = (const float*)d_in[6];  // [E]
    float* out = (float*)d_out;                      // [N, 128]

    const int M = in_sizes[0] / F_IN;
    const int E = in_sizes[4];

    // 1) x = (features * drop_mask) @ W
    gemm_dropout_kernel<<<(M + BM - 1) / BM, 256>>>(features, drop_mask, W, M);

    // 2) CSR build
    zero_deg_kernel<<<(M + 255) / 256, 256>>>(M);
    hist_kernel<<<(E + 255) / 256, 256>>>(adj_rows, E);
    scan_kernel<<<1, 1024>>>(M);
    fill_kernel<<<(E + 255) / 256, 256>>>(adj_rows, adj_cols, adj_vals, E);

    // 3) row-parallel SpMM + bias + ReLU (one warp per row, 8 warps/block)
    spmm_csr_kernel<<<(M + 7) / 8, 256>>>(b, out, M);
}

// round 4
// speedup vs baseline: 1.3718x; 1.2509x over previous
#include <cuda_runtime.h>
#include <cuda_bf16.h>
#include <cstdint>

// Problem constants (fixed by the dataset)
#define F_IN   512
#define F_OUT  128
#define MAX_N  50048
#define MAX_E  1700000

// Scratch for x = (features * drop_mask) @ W   [N, F_OUT]
__device__ float g_x[(size_t)MAX_N * F_OUT];

// CSR scratch
__device__ int   g_deg[MAX_N];
__device__ int   g_row_start[MAX_N + 1];
__device__ int   g_cursor[MAX_N];
__device__ int   g_blk_sum[512];
__device__ uint2 g_edges[MAX_E];   // .x = col, .y = bits(val)

// ---------------------------------------------------------------------------
// Packed f32x2 helpers (Blackwell FFMA2)
// ---------------------------------------------------------------------------
__device__ __forceinline__ void fma2(unsigned long long& d,
                                     unsigned long long a,
                                     unsigned long long b)
{
    asm("fma.rn.f32x2 %0, %1, %2, %0;" : "+l"(d) : "l"(a), "l"(b));
}

__device__ __forceinline__ unsigned long long splat2(float x)
{
    unsigned long long r;
    asm("mov.b64 %0, {%1, %1};" : "=l"(r) : "f"(x));
    return r;
}

__device__ __forceinline__ float2 unpack2(unsigned long long v)
{
    float2 f;
    asm("mov.b64 {%0, %1}, %2;" : "=f"(f.x), "=f"(f.y) : "l"(v));
    return f;
}

// ---------------------------------------------------------------------------
// Kernel 1: fused dropout + SGEMM (fp32, FFMA2 inner loop)
// ---------------------------------------------------------------------------
#define BM 128
#define BN 128
#define BK 16
#define TM 8
#define TN 8

__global__ __launch_bounds__(256, 2)
void gemm_dropout_kernel(const float* __restrict__ A,
                         const float* __restrict__ Mk,
                         const float* __restrict__ W,
                         int M)
{
    __shared__ float As[BK][BM];
    __shared__ float Bs[BK][BN];

    const int block_m = blockIdx.x * BM;
    const int tid = threadIdx.x;
    const int ty  = tid >> 4;
    const int tx  = tid & 15;

    unsigned long long acc2[TM][TN / 2];
#pragma unroll
    for (int i = 0; i < TM; i++)
#pragma unroll
        for (int j = 0; j < TN / 2; j++) acc2[i][j] = 0ull;

    for (int k0 = 0; k0 < F_IN; k0 += BK) {
#pragma unroll
        for (int p = 0; p < 2; p++) {
            int idx  = tid + p * 256;
            int row  = idx >> 2;
            int col4 = (idx & 3) * 4;
            int gm   = block_m + row;
            float4 av = make_float4(0.f, 0.f, 0.f, 0.f);
            if (gm < M) {
                const float4 a = *(const float4*)(A  + (size_t)gm * F_IN + k0 + col4);
                const float4 m = *(const float4*)(Mk + (size_t)gm * F_IN + k0 + col4);
                av = make_float4(a.x * m.x, a.y * m.y, a.z * m.z, a.w * m.w);
            }
            As[col4 + 0][row] = av.x;
            As[col4 + 1][row] = av.y;
            As[col4 + 2][row] = av.z;
            As[col4 + 3][row] = av.w;
        }
#pragma unroll
        for (int p = 0; p < 2; p++) {
            int idx  = tid + p * 256;
            int row  = idx >> 5;
            int col4 = (idx & 31) * 4;
            *(float4*)(&Bs[row][col4]) =
                *(const float4*)(W + (size_t)(k0 + row) * F_OUT + col4);
        }
        __syncthreads();

#pragma unroll
        for (int k = 0; k < BK; k++) {
            const float4 av0 = *(const float4*)(&As[k][ty * TM]);
            const float4 av1 = *(const float4*)(&As[k][ty * TM + 4]);
            unsigned long long a2[TM];
            a2[0] = splat2(av0.x); a2[1] = splat2(av0.y);
            a2[2] = splat2(av0.z); a2[3] = splat2(av0.w);
            a2[4] = splat2(av1.x); a2[5] = splat2(av1.y);
            a2[6] = splat2(av1.z); a2[7] = splat2(av1.w);

            const unsigned long long* bs =
                (const unsigned long long*)(&Bs[k][tx * TN]);
            unsigned long long b2[TN / 2];
            b2[0] = bs[0]; b2[1] = bs[1]; b2[2] = bs[2]; b2[3] = bs[3];

#pragma unroll
            for (int i = 0; i < TM; i++)
#pragma unroll
                for (int j = 0; j < TN / 2; j++)
                    fma2(acc2[i][j], a2[i], b2[j]);
        }
        __syncthreads();
    }

#pragma unroll
    for (int i = 0; i < TM; i++) {
        int gm = block_m + ty * TM + i;
        if (gm < M) {
            float* xr = g_x + (size_t)gm * F_OUT + tx * TN;
#pragma unroll
            for (int j = 0; j < TN / 2; j += 2) {
                float2 lo = unpack2(acc2[i][j]);
                float2 hi = unpack2(acc2[i][j + 1]);
                *(float4*)(xr + 2 * j) = make_float4(lo.x, lo.y, hi.x, hi.y);
            }
        }
    }
}

// ---------------------------------------------------------------------------
// CSR build step 1: zero degree counters
// ---------------------------------------------------------------------------
__global__ void zero_deg_kernel(int N)
{
    int i = blockIdx.x * blockDim.x + threadIdx.x;
    if (i < N) g_deg[i] = 0;
}

// ---------------------------------------------------------------------------
// CSR build step 2: histogram of row degrees
// ---------------------------------------------------------------------------
__global__ void hist_kernel(const int* __restrict__ rows, int E)
{
    int i = blockIdx.x * blockDim.x + threadIdx.x;
    if (i < E) atomicAdd(&g_deg[rows[i]], 1);
}

// ---------------------------------------------------------------------------
// Parallel scan: phase 1 — per-block (256-wide) exclusive scan of g_deg.
// Writes block-local exclusive prefix to g_row_start, block total to g_blk_sum.
// ---------------------------------------------------------------------------
__global__ __launch_bounds__(256)
void scan_blocks_kernel(int N)
{
    __shared__ int sh[256];
    const int tid = threadIdx.x;
    const int i = blockIdx.x * 256 + tid;

    int v = (i < N) ? g_deg[i] : 0;
    int incl = v;
    sh[tid] = incl;
    __syncthreads();
#pragma unroll
    for (int off = 1; off < 256; off <<= 1) {
        int t = (tid >= off) ? sh[tid - off] : 0;
        __syncthreads();
        incl += t;
        sh[tid] = incl;
        __syncthreads();
    }
    if (i < N) g_row_start[i] = incl - v;   // block-local exclusive
    if (tid == 255) g_blk_sum[blockIdx.x] = incl;
}

// ---------------------------------------------------------------------------
// Parallel scan: phase 2 — exclusive scan of block sums (single block).
// ---------------------------------------------------------------------------
__global__ __launch_bounds__(512)
void scan_top_kernel(int nblocks)
{
    __shared__ int sh[512];
    const int tid = threadIdx.x;
    int v = (tid < nblocks) ? g_blk_sum[tid] : 0;
    int incl = v;
    sh[tid] = incl;
    __syncthreads();
#pragma unroll
    for (int off = 1; off < 512; off <<= 1) {
        int t = (tid >= off) ? sh[tid - off] : 0;
        __syncthreads();
        incl += t;
        sh[tid] = incl;
        __syncthreads();
    }
    if (tid < nblocks) g_blk_sum[tid] = incl - v;   // exclusive
}

// ---------------------------------------------------------------------------
// Parallel scan: phase 3 — add block offsets, seed cursors, close row_start.
// ---------------------------------------------------------------------------
__global__ __launch_bounds__(256)
void scan_add_kernel(int N, int E)
{
    const int i = blockIdx.x * 256 + threadIdx.x;
    if (i < N) {
        int rs = g_row_start[i] + g_blk_sum[blockIdx.x];
        g_row_start[i] = rs;
        g_cursor[i]    = rs;
    }
    if (i == 0) g_row_start[N] = E;
}

// ---------------------------------------------------------------------------
// CSR build step 4: bucket fill (packed col+val)
// ---------------------------------------------------------------------------
__global__ void fill_kernel(const int*   __restrict__ rows,
                            const int*   __restrict__ cols,
                            const float* __restrict__ vals,
                            int E)
{
    int i = blockIdx.x * blockDim.x + threadIdx.x;
    if (i < E) {
        int pos = atomicAdd(&g_cursor[rows[i]], 1);
        g_edges[pos] = make_uint2((unsigned)cols[i], __float_as_uint(vals[i]));
    }
}

// ---------------------------------------------------------------------------
// Kernel 5: row-parallel SpMM + bias + ReLU (one warp per output row)
// Each lane owns one float4 (32 lanes x 4 = 128 = F_OUT). 4-edge unroll.
// ---------------------------------------------------------------------------
__global__ __launch_bounds__(256)
void spmm_csr_kernel(const float* __restrict__ b,
                     float*       __restrict__ out,
                     int N)
{
    const int warp_in_blk = threadIdx.x >> 5;
    const int lane = threadIdx.x & 31;
    const int row  = blockIdx.x * 8 + warp_in_blk;
    if (row >= N) return;

    const int s = g_row_start[row];
    const int e = g_row_start[row + 1];

    float4 acc = make_float4(0.f, 0.f, 0.f, 0.f);

    int j = s;
    for (; j + 4 <= e; j += 4) {
        const uint2 e0 = g_edges[j];
        const uint2 e1 = g_edges[j + 1];
        const uint2 e2 = g_edges[j + 2];
        const uint2 e3 = g_edges[j + 3];
        const float4 a0 = __ldg((const float4*)(g_x + (size_t)e0.x * F_OUT) + lane);
        const float4 a1 = __ldg((const float4*)(g_x + (size_t)e1.x * F_OUT) + lane);
        const float4 a2 = __ldg((const float4*)(g_x + (size_t)e2.x * F_OUT) + lane);
        const float4 a3 = __ldg((const float4*)(g_x + (size_t)e3.x * F_OUT) + lane);
        const float v0 = __uint_as_float(e0.y);
        const float v1 = __uint_as_float(e1.y);
        const float v2 = __uint_as_float(e2.y);
        const float v3 = __uint_as_float(e3.y);
        acc.x = fmaf(v0, a0.x, acc.x); acc.y = fmaf(v0, a0.y, acc.y);
        acc.z = fmaf(v0, a0.z, acc.z); acc.w = fmaf(v0, a0.w, acc.w);
        acc.x = fmaf(v1, a1.x, acc.x); acc.y = fmaf(v1, a1.y, acc.y);
        acc.z = fmaf(v1, a1.z, acc.z); acc.w = fmaf(v1, a1.w, acc.w);
        acc.x = fmaf(v2, a2.x, acc.x); acc.y = fmaf(v2, a2.y, acc.y);
        acc.z = fmaf(v2, a2.z, acc.z); acc.w = fmaf(v2, a2.w, acc.w);
        acc.x = fmaf(v3, a3.x, acc.x); acc.y = fmaf(v3, a3.y, acc.y);
        acc.z = fmaf(v3, a3.z, acc.z); acc.w = fmaf(v3, a3.w, acc.w);
    }
    for (; j < e; j++) {
        const uint2 e0 = g_edges[j];
        const float4 a0 = __ldg((const float4*)(g_x + (size_t)e0.x * F_OUT) + lane);
        const float v0 = __uint_as_float(e0.y);
        acc.x = fmaf(v0, a0.x, acc.x); acc.y = fmaf(v0, a0.y, acc.y);
        acc.z = fmaf(v0, a0.z, acc.z); acc.w = fmaf(v0, a0.w, acc.w);
    }

    // fused bias + ReLU
    const float4 bb = ((const float4*)b)[lane];
    float4 r;
    r.x = fmaxf(acc.x + bb.x, 0.f);
    r.y = fmaxf(acc.y + bb.y, 0.f);
    r.z = fmaxf(acc.z + bb.z, 0.f);
    r.w = fmaxf(acc.w + bb.w, 0.f);
    ((float4*)(out + (size_t)row * F_OUT))[lane] = r;
}

// ---------------------------------------------------------------------------
extern "C" void kernel_launch(void* const* d_in, const int* in_sizes, int n_in,
                              void* d_out, int out_size)
{
    const float* features  = (const float*)d_in[0];  // [N, 512]
    const float* drop_mask = (const float*)d_in[1];  // [N, 512]
    const float* W         = (const float*)d_in[2];  // [512, 128]
    const float* b         = (const float*)d_in[3];  // [128]
    const int*   adj_rows  = (const int*)d_in[4];    // [E]
    const int*   adj_cols  = (const int*)d_in[5];    // [E]
    const float* adj_vals  = (const float*)d_in[6];  // [E]
    float* out = (float*)d_out;                      // [N, 128]

    const int M = in_sizes[0] / F_IN;
    const int E = in_sizes[4];
    const int nscan = (M + 255) / 256;               // <= 512

    // 1) x = (features * drop_mask) @ W
    gemm_dropout_kernel<<<(M + BM - 1) / BM, 256>>>(features, drop_mask, W, M);

    // 2) CSR build (parallel 3-phase scan)
    zero_deg_kernel<<<(M + 255) / 256, 256>>>(M);
    hist_kernel<<<(E + 255) / 256, 256>>>(adj_rows, E);
    scan_blocks_kernel<<<nscan, 256>>>(M);
    scan_top_kernel<<<1, 512>>>(nscan);
    scan_add_kernel<<<nscan, 256>>>(M, E);
    fill_kernel<<<(E + 255) / 256, 256>>>(adj_rows, adj_cols, adj_vals, E);

    // 3) row-parallel SpMM + bias + ReLU (one warp per row, 8 warps/block)
    spmm_csr_kernel<<<(M + 7) / 8, 256>>>(b, out, M);
}

// round 5
// speedup vs baseline: 1.8521x; 1.3501x over previous
#include <cuda_runtime.h>
#include <cuda_bf16.h>
#include <cstdint>

// Problem constants (fixed by the dataset)
#define F_IN   512
#define F_OUT  128
#define MAX_N  50048
#define MAX_E  1700000

// Scratch for x = (features * drop_mask) @ W   [N, F_OUT]
__device__ float g_x[(size_t)MAX_N * F_OUT];

// CSR scratch
__device__ int   g_deg[MAX_N];
__device__ int   g_row_start[MAX_N + 1];
__device__ int   g_cursor[MAX_N];
__device__ int   g_blk_sum[512];
__device__ uint2 g_edges[MAX_E];   // .x = col, .y = bits(val)

// ---------------------------------------------------------------------------
// Kernel 1: fused dropout + split-bf16 tensor-core GEMM
// x = (A .* Mk) @ W,  A:[M,512] fp32, W:[512,128] fp32, x:[M,128] fp32
// Split: v = hi + lo (bf16 each); x ~= Ah*Wh + Ah*Wl + Al*Wh  (err ~1e-5)
// Tiles: BM=128, BN=128, BK=32; 256 threads = 8 warps (4 along M x 2 along N),
// each warp computes 32x64 via m16n8k16 mma.sync.
// ---------------------------------------------------------------------------
#define BM 128
#define BK 32
#define LDA 40    // As row length (bf16) with +8 pad: conflict-free ldmatrix
#define LDB 136   // Ws row length (bf16) with +8 pad

__device__ __forceinline__ void ldm_x4(uint32_t* f, uint32_t addr)
{
    asm volatile("ldmatrix.sync.aligned.m8n8.x4.shared.b16 {%0,%1,%2,%3}, [%4];"
                 : "=r"(f[0]), "=r"(f[1]), "=r"(f[2]), "=r"(f[3]) : "r"(addr));
}

__device__ __forceinline__ void ldm_x4_trans(uint32_t* f, uint32_t addr)
{
    asm volatile("ldmatrix.sync.aligned.m8n8.x4.trans.shared.b16 {%0,%1,%2,%3}, [%4];"
                 : "=r"(f[0]), "=r"(f[1]), "=r"(f[2]), "=r"(f[3]) : "r"(addr));
}

__device__ __forceinline__ void mma_bf16(float* c, const uint32_t* a,
                                         uint32_t b0, uint32_t b1)
{
    asm volatile(
        "mma.sync.aligned.m16n8k16.row.col.f32.bf16.bf16.f32 "
        "{%0,%1,%2,%3}, {%4,%5,%6,%7}, {%8,%9}, {%0,%1,%2,%3};"
        : "+f"(c[0]), "+f"(c[1]), "+f"(c[2]), "+f"(c[3])
        : "r"(a[0]), "r"(a[1]), "r"(a[2]), "r"(a[3]), "r"(b0), "r"(b1));
}

__device__ __forceinline__ uint32_t smem_u32(const void* p)
{
    uint32_t r;
    asm("{.reg .u64 t; cvta.to.shared.u64 t, %1; cvt.u32.u64 %0, t;}"
        : "=r"(r) : "l"(p));
    return r;
}

__device__ __forceinline__ uint32_t pack_bf16x2(float lo_val, float hi_val)
{
    __nv_bfloat162 h = __floats2bfloat162_rn(lo_val, hi_val); // .x=lo elem,.y=hi elem
    return *(uint32_t*)&h;
}

__global__ __launch_bounds__(256)
void gemm_dropout_mma_kernel(const float* __restrict__ A,
                             const float* __restrict__ Mk,
                             const float* __restrict__ W,
                             int M)
{
    __shared__ __nv_bfloat16 As_hi[BM][LDA];
    __shared__ __nv_bfloat16 As_lo[BM][LDA];
    __shared__ __nv_bfloat16 Ws_hi[BK][LDB];
    __shared__ __nv_bfloat16 Ws_lo[BK][LDB];

    const int tid  = threadIdx.x;
    const int warp = tid >> 5;
    const int lane = tid & 31;
    const int block_m = blockIdx.x * BM;

    const int wm = (warp & 3) * 32;   // warp m-offset (0,32,64,96)
    const int wn = (warp >> 2) * 64;  // warp n-offset (0,64)

    // ldmatrix lane geometry (same pattern for A and for B-trans)
    const int aRow = lane & 15;           // row within 16
    const int aOff = (lane >> 4) * 8;     // second 8-col/8-n half

    float acc[2][8][4];
#pragma unroll
    for (int mt = 0; mt < 2; mt++)
#pragma unroll
        for (int nt = 0; nt < 8; nt++)
#pragma unroll
            for (int q = 0; q < 4; q++) acc[mt][nt][q] = 0.f;

    const uint32_t as_hi_b = smem_u32(&As_hi[0][0]);
    const uint32_t as_lo_b = smem_u32(&As_lo[0][0]);
    const uint32_t ws_hi_b = smem_u32(&Ws_hi[0][0]);
    const uint32_t ws_lo_b = smem_u32(&Ws_lo[0][0]);

    for (int k0 = 0; k0 < F_IN; k0 += BK) {
        // ---- fill A tiles: 128x32 fp32, fused dropout, split to hi/lo ----
        // 1024 float4 total, 4 per thread
#pragma unroll
        for (int p = 0; p < 4; p++) {
            int idx = p * 256 + tid;
            int row = idx >> 3;            // 0..127
            int col = (idx & 7) * 4;       // 0..28
            int gm  = block_m + row;
            float4 e = make_float4(0.f, 0.f, 0.f, 0.f);
            if (gm < M) {
                const float4 a = *(const float4*)(A  + (size_t)gm * F_IN + k0 + col);
                const float4 m = *(const float4*)(Mk + (size_t)gm * F_IN + k0 + col);
                e = make_float4(a.x * m.x, a.y * m.y, a.z * m.z, a.w * m.w);
            }
            float eh[4], el[4];
            const float ev[4] = {e.x, e.y, e.z, e.w};
#pragma unroll
            for (int q = 0; q < 4; q++) {
                __nv_bfloat16 h = __float2bfloat16(ev[q]);
                eh[q] = __bfloat162float(h);
                el[q] = ev[q] - eh[q];
            }
            uint2 hw, lw;
            hw.x = pack_bf16x2(eh[0], eh[1]); hw.y = pack_bf16x2(eh[2], eh[3]);
            lw.x = pack_bf16x2(el[0], el[1]); lw.y = pack_bf16x2(el[2], el[3]);
            *(uint2*)&As_hi[row][col] = hw;
            *(uint2*)&As_lo[row][col] = lw;
        }
        // ---- fill W tiles: 32x128 fp32, split to hi/lo ----
#pragma unroll
        for (int p = 0; p < 4; p++) {
            int idx = p * 256 + tid;
            int row = idx >> 5;            // 0..31
            int col = (idx & 31) * 4;      // 0..124
            const float4 w = *(const float4*)(W + (size_t)(k0 + row) * F_OUT + col);
            float eh[4], el[4];
            const float wv[4] = {w.x, w.y, w.z, w.w};
#pragma unroll
            for (int q = 0; q < 4; q++) {
                __nv_bfloat16 h = __float2bfloat16(wv[q]);
                eh[q] = __bfloat162float(h);
                el[q] = wv[q] - eh[q];
            }
            uint2 hw, lw;
            hw.x = pack_bf16x2(eh[0], eh[1]); hw.y = pack_bf16x2(eh[2], eh[3]);
            lw.x = pack_bf16x2(el[0], el[1]); lw.y = pack_bf16x2(el[2], el[3]);
            *(uint2*)&Ws_hi[row][col] = hw;
            *(uint2*)&Ws_lo[row][col] = lw;
        }
        __syncthreads();

        // ---- compute: two k16 steps per chunk ----
#pragma unroll
        for (int k16 = 0; k16 < BK; k16 += 16) {
            // A fragments (hi & lo) for both 16-row tiles
            uint32_t ah[2][4], al[2][4];
#pragma unroll
            for (int mt = 0; mt < 2; mt++) {
                int r = wm + mt * 16 + aRow;
                int c = k16 + aOff;
                ldm_x4(ah[mt], as_hi_b + (uint32_t)(r * LDA + c) * 2);
                ldm_x4(al[mt], as_lo_b + (uint32_t)(r * LDA + c) * 2);
            }
            // B fragments (hi & lo): 4 x (two n8 tiles) covering 64 cols
            uint32_t bh[4][4], bl[4][4];
#pragma unroll
            for (int nq = 0; nq < 4; nq++) {
                int kr = k16 + (lane & 15);
                int c  = wn + nq * 16 + aOff;
                ldm_x4_trans(bh[nq], ws_hi_b + (uint32_t)(kr * LDB + c) * 2);
                ldm_x4_trans(bl[nq], ws_lo_b + (uint32_t)(kr * LDB + c) * 2);
            }
            // 3 passes: Ah*Wh, Ah*Wl, Al*Wh
#pragma unroll
            for (int mt = 0; mt < 2; mt++) {
#pragma unroll
                for (int nt = 0; nt < 8; nt++) {
                    const int nq = nt >> 1, pr = (nt & 1) * 2;
                    mma_bf16(acc[mt][nt], ah[mt], bh[nq][pr], bh[nq][pr + 1]);
                    mma_bf16(acc[mt][nt], ah[mt], bl[nq][pr], bl[nq][pr + 1]);
                    mma_bf16(acc[mt][nt], al[mt], bh[nq][pr], bh[nq][pr + 1]);
                }
            }
        }
        __syncthreads();
    }

    // ---- store x tile ----
    const int gid = lane >> 2;       // 0..7
    const int tq  = lane & 3;        // 0..3
#pragma unroll
    for (int mt = 0; mt < 2; mt++) {
        int gm0 = block_m + wm + mt * 16 + gid;
        int gm1 = gm0 + 8;
#pragma unroll
        for (int nt = 0; nt < 8; nt++) {
            int col = wn + nt * 8 + tq * 2;
            if (gm0 < M)
                *(float2*)(g_x + (size_t)gm0 * F_OUT + col) =
                    make_float2(acc[mt][nt][0], acc[mt][nt][1]);
            if (gm1 < M)
                *(float2*)(g_x + (size_t)gm1 * F_OUT + col) =
                    make_float2(acc[mt][nt][2], acc[mt][nt][3]);
        }
    }
}

// ---------------------------------------------------------------------------
// CSR build step 1: zero degree counters
// ---------------------------------------------------------------------------
__global__ void zero_deg_kernel(int N)
{
    int i = blockIdx.x * blockDim.x + threadIdx.x;
    if (i < N) g_deg[i] = 0;
}

// ---------------------------------------------------------------------------
// CSR build step 2: histogram of row degrees
// ---------------------------------------------------------------------------
__global__ void hist_kernel(const int* __restrict__ rows, int E)
{
    int i = blockIdx.x * blockDim.x + threadIdx.x;
    if (i < E) atomicAdd(&g_deg[rows[i]], 1);
}

// ---------------------------------------------------------------------------
// Parallel scan: phase 1 — per-block (256-wide) exclusive scan of g_deg.
// ---------------------------------------------------------------------------
__global__ __launch_bounds__(256)
void scan_blocks_kernel(int N)
{
    __shared__ int sh[256];
    const int tid = threadIdx.x;
    const int i = blockIdx.x * 256 + tid;

    int v = (i < N) ? g_deg[i] : 0;
    int incl = v;
    sh[tid] = incl;
    __syncthreads();
#pragma unroll
    for (int off = 1; off < 256; off <<= 1) {
        int t = (tid >= off) ? sh[tid - off] : 0;
        __syncthreads();
        incl += t;
        sh[tid] = incl;
        __syncthreads();
    }
    if (i < N) g_row_start[i] = incl - v;
    if (tid == 255) g_blk_sum[blockIdx.x] = incl;
}

// ---------------------------------------------------------------------------
// Parallel scan: phase 2 — exclusive scan of block sums (single block).
// ---------------------------------------------------------------------------
__global__ __launch_bounds__(512)
void scan_top_kernel(int nblocks)
{
    __shared__ int sh[512];
    const int tid = threadIdx.x;
    int v = (tid < nblocks) ? g_blk_sum[tid] : 0;
    int incl = v;
    sh[tid] = incl;
    __syncthreads();
#pragma unroll
    for (int off = 1; off < 512; off <<= 1) {
        int t = (tid >= off) ? sh[tid - off] : 0;
        __syncthreads();
        incl += t;
        sh[tid] = incl;
        __syncthreads();
    }
    if (tid < nblocks) g_blk_sum[tid] = incl - v;
}

// ---------------------------------------------------------------------------
// Parallel scan: phase 3 — add block offsets, seed cursors, close row_start.
// ---------------------------------------------------------------------------
__global__ __launch_bounds__(256)
void scan_add_kernel(int N, int E)
{
    const int i = blockIdx.x * 256 + threadIdx.x;
    if (i < N) {
        int rs = g_row_start[i] + g_blk_sum[blockIdx.x];
        g_row_start[i] = rs;
        g_cursor[i]    = rs;
    }
    if (i == 0) g_row_start[N] = E;
}

// ---------------------------------------------------------------------------
// CSR build step 4: bucket fill (packed col+val)
// ---------------------------------------------------------------------------
__global__ void fill_kernel(const int*   __restrict__ rows,
                            const int*   __restrict__ cols,
                            const float* __restrict__ vals,
                            int E)
{
    int i = blockIdx.x * blockDim.x + threadIdx.x;
    if (i < E) {
        int pos = atomicAdd(&g_cursor[rows[i]], 1);
        g_edges[pos] = make_uint2((unsigned)cols[i], __float_as_uint(vals[i]));
    }
}

// ---------------------------------------------------------------------------
// Kernel 5: row-parallel SpMM + bias + ReLU (one warp per output row)
// ---------------------------------------------------------------------------
__global__ __launch_bounds__(256)
void spmm_csr_kernel(const float* __restrict__ b,
                     float*       __restrict__ out,
                     int N)
{
    const int warp_in_blk = threadIdx.x >> 5;
    const int lane = threadIdx.x & 31;
    const int row  = blockIdx.x * 8 + warp_in_blk;
    if (row >= N) return;

    const int s = g_row_start[row];
    const int e = g_row_start[row + 1];

    float4 acc = make_float4(0.f, 0.f, 0.f, 0.f);

    int j = s;
    for (; j + 4 <= e; j += 4) {
        const uint2 e0 = g_edges[j];
        const uint2 e1 = g_edges[j + 1];
        const uint2 e2 = g_edges[j + 2];
        const uint2 e3 = g_edges[j + 3];
        const float4 a0 = __ldg((const float4*)(g_x + (size_t)e0.x * F_OUT) + lane);
        const float4 a1 = __ldg((const float4*)(g_x + (size_t)e1.x * F_OUT) + lane);
        const float4 a2 = __ldg((const float4*)(g_x + (size_t)e2.x * F_OUT) + lane);
        const float4 a3 = __ldg((const float4*)(g_x + (size_t)e3.x * F_OUT) + lane);
        const float v0 = __uint_as_float(e0.y);
        const float v1 = __uint_as_float(e1.y);
        const float v2 = __uint_as_float(e2.y);
        const float v3 = __uint_as_float(e3.y);
        acc.x = fmaf(v0, a0.x, acc.x); acc.y = fmaf(v0, a0.y, acc.y);
        acc.z = fmaf(v0, a0.z, acc.z); acc.w = fmaf(v0, a0.w, acc.w);
        acc.x = fmaf(v1, a1.x, acc.x); acc.y = fmaf(v1, a1.y, acc.y);
        acc.z = fmaf(v1, a1.z, acc.z); acc.w = fmaf(v1, a1.w, acc.w);
        acc.x = fmaf(v2, a2.x, acc.x); acc.y = fmaf(v2, a2.y, acc.y);
        acc.z = fmaf(v2, a2.z, acc.z); acc.w = fmaf(v2, a2.w, acc.w);
        acc.x = fmaf(v3, a3.x, acc.x); acc.y = fmaf(v3, a3.y, acc.y);
        acc.z = fmaf(v3, a3.z, acc.z); acc.w = fmaf(v3, a3.w, acc.w);
    }
    for (; j < e; j++) {
        const uint2 e0 = g_edges[j];
        const float4 a0 = __ldg((const float4*)(g_x + (size_t)e0.x * F_OUT) + lane);
        const float v0 = __uint_as_float(e0.y);
        acc.x = fmaf(v0, a0.x, acc.x); acc.y = fmaf(v0, a0.y, acc.y);
        acc.z = fmaf(v0, a0.z, acc.z); acc.w = fmaf(v0, a0.w, acc.w);
    }

    const float4 bb = ((const float4*)b)[lane];
    float4 r;
    r.x = fmaxf(acc.x + bb.x, 0.f);
    r.y = fmaxf(acc.y + bb.y, 0.f);
    r.z = fmaxf(acc.z + bb.z, 0.f);
    r.w = fmaxf(acc.w + bb.w, 0.f);
    ((float4*)(out + (size_t)row * F_OUT))[lane] = r;
}

// ---------------------------------------------------------------------------
extern "C" void kernel_launch(void* const* d_in, const int* in_sizes, int n_in,
                              void* d_out, int out_size)
{
    const float* features  = (const float*)d_in[0];  // [N, 512]
    const float* drop_mask = (const float*)d_in[1];  // [N, 512]
    const float* W         = (const float*)d_in[2];  // [512, 128]
    const float* b         = (const float*)d_in[3];  // [128]
    const int*   adj_rows  = (const int*)d_in[4];    // [E]
    const int*   adj_cols  = (const int*)d_in[5];    // [E]
    const float* adj_vals  = (const float*)d_in[6];  // [E]
    float* out = (float*)d_out;                      // [N, 128]

    const int M = in_sizes[0] / F_IN;
    const int E = in_sizes[4];
    const int nscan = (M + 255) / 256;

    // 1) x = (features * drop_mask) @ W   (split-bf16 tensor cores)
    gemm_dropout_mma_kernel<<<(M + BM - 1) / BM, 256>>>(features, drop_mask, W, M);

    // 2) CSR build (parallel 3-phase scan)
    zero_deg_kernel<<<(M + 255) / 256, 256>>>(M);
    hist_kernel<<<(E + 255) / 256, 256>>>(adj_rows, E);
    scan_blocks_kernel<<<nscan, 256>>>(M);
    scan_top_kernel<<<1, 512>>>(nscan);
    scan_add_kernel<<<nscan, 256>>>(M, E);
    fill_kernel<<<(E + 255) / 256, 256>>>(adj_rows, adj_cols, adj_vals, E);

    // 3) row-parallel SpMM + bias + ReLU
    spmm_csr_kernel<<<(M + 7) / 8, 256>>>(b, out, M);
}